// round 1
// baseline (speedup 1.0000x reference)
#include <cuda_runtime.h>

#define BATCH 4
#define NP    4096
#define MQ    4096
#define CC    16
#define KMAX  128

// Output layout (float elements)
#define OFF_LOCS 0
#define OFF_DATA (BATCH*NP*3)                       // 49152
#define OFF_IDXS (OFF_DATA + BATCH*NP*CC)           // 311296
#define OFF_NEI  (OFF_IDXS + BATCH*NP)              // 327680

// ---- device scratch (no allocations allowed) ----
__device__ float        g_low[BATCH][3];
__device__ float        g_gdimf[BATCH][3];
__device__ int          g_stride[BATCH][3];
__device__ unsigned int g_keys[BATCH * NP];
__device__ float4       g_p4[BATCH * NP];   // reordered particles: x,y,z,|p|^2

// ---------------------------------------------------------------------------
// Kernel 1: per-batch bounds -> grid params. One block per batch.
// Replicates the jnp arithmetic exactly (no FMA contraction, IEEE div).
// ---------------------------------------------------------------------------
__global__ void k_bounds(const float* __restrict__ locs) {
    const int b = blockIdx.x;
    const int t = threadIdx.x;

    float mn0 = 1e30f, mn1 = 1e30f, mn2 = 1e30f;
    float mx0 = -1e30f, mx1 = -1e30f, mx2 = -1e30f;
    for (int i = t; i < NP; i += blockDim.x) {
        const float* p = locs + (size_t)(b * NP + i) * 3;
        float v0 = p[0], v1 = p[1], v2 = p[2];
        mn0 = fminf(mn0, v0); mx0 = fmaxf(mx0, v0);
        mn1 = fminf(mn1, v1); mx1 = fmaxf(mx1, v1);
        mn2 = fminf(mn2, v2); mx2 = fmaxf(mx2, v2);
    }

    __shared__ float smn[3][256];
    __shared__ float smx[3][256];
    smn[0][t] = mn0; smn[1][t] = mn1; smn[2][t] = mn2;
    smx[0][t] = mx0; smx[1][t] = mx1; smx[2][t] = mx2;
    __syncthreads();
    for (int s = 128; s > 0; s >>= 1) {
        if (t < s) {
            #pragma unroll
            for (int d = 0; d < 3; d++) {
                smn[d][t] = fminf(smn[d][t], smn[d][t + s]);
                smx[d][t] = fmaxf(smx[d][t], smx[d][t + s]);
            }
        }
        __syncthreads();
    }

    if (t == 0) {
        int gd[3];
        #pragma unroll
        for (int d = 0; d < 3; d++) {
            float lo = smn[d][0];
            float up = smx[d][0];
            float diff = __fsub_rn(up, lo);
            float gdf  = ceilf(fminf(fmaxf(__fdiv_rn(diff, 0.14f), 0.0f), 96.0f));
            float center = __fmul_rn(__fadd_rn(lo, up), 0.5f);
            float half   = __fmul_rn(__fmul_rn(gdf, 0.14f), 0.5f);
            float low2   = __fsub_rn(center, half);
            g_low[b][d]   = low2;
            g_gdimf[b][d] = gdf;
            int gi = (int)gdf;
            gd[d] = gi > 1 ? gi : 1;
        }
        g_stride[b][0] = gd[1] * gd[2];
        g_stride[b][1] = gd[2];
        g_stride[b][2] = 1;
    }
}

// ---------------------------------------------------------------------------
// Kernel 2: composite sort keys. key = (cell_id << 12) | particle_index
// cell_id < 96^3 < 2^20, index < 2^12 -> fits uint32, unique keys, so a
// plain sort of keys reproduces jnp's stable argsort by cell id.
// ---------------------------------------------------------------------------
__global__ void k_keys(const float* __restrict__ locs) {
    int i = blockIdx.x * blockDim.x + threadIdx.x;
    if (i >= BATCH * NP) return;
    int b = i / NP;
    const float* p = locs + (size_t)i * 3;
    unsigned int id = 0;
    #pragma unroll
    for (int d = 0; d < 3; d++) {
        float c = floorf(__fdiv_rn(__fsub_rn(p[d], g_low[b][d]), 0.14f));
        c = fminf(fmaxf(c, 0.0f), __fsub_rn(g_gdimf[b][d], 1.0f));
        id += (unsigned int)((int)c * g_stride[b][d]);
    }
    g_keys[i] = (id << 12) | (unsigned int)(i - b * NP);
}

// ---------------------------------------------------------------------------
// Kernel 3: rank-by-count sort + fused scatter of all per-particle outputs.
// grid = (16, BATCH), 256 threads. Keys staged in SMEM; inner loop is
// broadcast LDS + compare.
// ---------------------------------------------------------------------------
__global__ void k_rank_scatter(const float* __restrict__ locs,
                               const float* __restrict__ data,
                               float* __restrict__ out) {
    const int b = blockIdx.y;
    __shared__ unsigned int sk[NP];
    for (int j = threadIdx.x; j < NP; j += blockDim.x)
        sk[j] = g_keys[b * NP + j];
    __syncthreads();

    const int i = blockIdx.x * blockDim.x + threadIdx.x;   // 0..NP-1
    const unsigned int my = sk[i];
    int r = 0;
    #pragma unroll 16
    for (int j = 0; j < NP; j++)
        r += (sk[j] < my) ? 1 : 0;

    const int src = b * NP + i;
    const int dst = b * NP + r;

    const float* p = locs + (size_t)src * 3;
    float x = p[0], y = p[1], z = p[2];
    float pn = x * x + y * y + z * z;

    out[OFF_LOCS + (size_t)dst * 3 + 0] = x;
    out[OFF_LOCS + (size_t)dst * 3 + 1] = y;
    out[OFF_LOCS + (size_t)dst * 3 + 2] = z;
    g_p4[dst] = make_float4(x, y, z, pn);

    out[OFF_IDXS + dst] = (float)i;

    const float4* d4 = (const float4*)data;      // CC=16 -> 4 float4 per row
    float4* o4 = (float4*)(out + OFF_DATA);
    #pragma unroll
    for (int k = 0; k < 4; k++)
        o4[(size_t)dst * 4 + k] = d4[(size_t)src * 4 + k];
}

// ---------------------------------------------------------------------------
// Kernel 4: radius search. grid = (MQ/128, BATCH), 128 threads.
// Whole reordered batch (4096 x float4 = 64KB) in dynamic SMEM; each thread
// scans j ascending -> neighbor list naturally in ascending reordered order.
// dist2 = (qn + pn) - 2*cross, identical to the reference formula.
// ---------------------------------------------------------------------------
__global__ void k_neighbors(const float* __restrict__ qlocs,
                            float* __restrict__ out) {
    extern __shared__ float4 sp[];
    const int b = blockIdx.y;
    for (int j = threadIdx.x; j < NP; j += blockDim.x)
        sp[j] = g_p4[b * NP + j];
    __syncthreads();

    const int m = blockIdx.x * blockDim.x + threadIdx.x;
    const float* q = qlocs + (size_t)(b * MQ + m) * 3;
    const float q0 = q[0], q1 = q[1], q2 = q[2];
    const float qn = q0 * q0 + q1 * q1 + q2 * q2;
    const float R2 = (float)(0.14 * 0.14);

    float* no = out + OFF_NEI + (size_t)(b * MQ + m) * KMAX;
    int cnt = 0;
    #pragma unroll 4
    for (int j = 0; j < NP; j++) {
        float4 p = sp[j];
        float cross = q0 * p.x + q1 * p.y + q2 * p.z;
        float d2 = (qn + p.w) - 2.0f * cross;
        if (d2 <= R2) {
            if (cnt < KMAX) no[cnt] = (float)j;
            cnt++;
        }
    }
    if (cnt > KMAX) cnt = KMAX;
    for (int k = cnt; k < KMAX; k++)
        no[k] = -1.0f;
}

// ---------------------------------------------------------------------------
extern "C" void kernel_launch(void* const* d_in, const int* in_sizes, int n_in,
                              void* d_out, int out_size) {
    const float* locs  = (const float*)d_in[0];   // [B,N,3]
    const float* data  = (const float*)d_in[1];   // [B,N,16]
    const float* qlocs = (const float*)d_in[2];   // [B,M,3]
    float* out = (float*)d_out;

    k_bounds<<<BATCH, 256>>>(locs);
    k_keys<<<(BATCH * NP + 255) / 256, 256>>>(locs);

    dim3 g3(NP / 256, BATCH);
    k_rank_scatter<<<g3, 256>>>(locs, data, out);

    cudaFuncSetAttribute(k_neighbors,
                         cudaFuncAttributeMaxDynamicSharedMemorySize,
                         NP * (int)sizeof(float4));
    dim3 g4(MQ / 128, BATCH);
    k_neighbors<<<g4, 128, NP * sizeof(float4)>>>(qlocs, out);
}

// round 2
// speedup vs baseline: 2.6773x; 2.6773x over previous
#include <cuda_runtime.h>

#define BATCH 4
#define NP    4096
#define MQ    4096
#define CC    16
#define KMAX  128
#define MAXCELLS (96*96*96 + 1)

// Output layout (float elements)
#define OFF_LOCS 0
#define OFF_DATA (BATCH*NP*3)                       // 49152
#define OFF_IDXS (OFF_DATA + BATCH*NP*CC)           // 311296
#define OFF_NEI  (OFF_IDXS + BATCH*NP)              // 327680

// ---- device scratch (no allocations allowed) ----
__device__ float        g_low[BATCH][3];
__device__ float        g_gdimf[BATCH][3];
__device__ int          g_stride[BATCH][3];
__device__ int          g_ncell[BATCH];
__device__ unsigned int g_keys[BATCH * NP];
__device__ int          g_scell[BATCH * NP];       // sorted cell id per reordered slot
__device__ float4       g_p4[BATCH * NP];          // reordered particles: x,y,z,|p|^2
__device__ int          g_cellstart[BATCH][MAXCELLS];

// ---------------------------------------------------------------------------
// Kernel 1: per-batch bounds -> grid params. One block per batch.
// ---------------------------------------------------------------------------
__global__ void k_bounds(const float* __restrict__ locs) {
    const int b = blockIdx.x;
    const int t = threadIdx.x;

    float mn0 = 1e30f, mn1 = 1e30f, mn2 = 1e30f;
    float mx0 = -1e30f, mx1 = -1e30f, mx2 = -1e30f;
    for (int i = t; i < NP; i += blockDim.x) {
        const float* p = locs + (size_t)(b * NP + i) * 3;
        float v0 = p[0], v1 = p[1], v2 = p[2];
        mn0 = fminf(mn0, v0); mx0 = fmaxf(mx0, v0);
        mn1 = fminf(mn1, v1); mx1 = fmaxf(mx1, v1);
        mn2 = fminf(mn2, v2); mx2 = fmaxf(mx2, v2);
    }

    __shared__ float smn[3][256];
    __shared__ float smx[3][256];
    smn[0][t] = mn0; smn[1][t] = mn1; smn[2][t] = mn2;
    smx[0][t] = mx0; smx[1][t] = mx1; smx[2][t] = mx2;
    __syncthreads();
    for (int s = 128; s > 0; s >>= 1) {
        if (t < s) {
            #pragma unroll
            for (int d = 0; d < 3; d++) {
                smn[d][t] = fminf(smn[d][t], smn[d][t + s]);
                smx[d][t] = fmaxf(smx[d][t], smx[d][t + s]);
            }
        }
        __syncthreads();
    }

    if (t == 0) {
        int gd[3];
        #pragma unroll
        for (int d = 0; d < 3; d++) {
            float lo = smn[d][0];
            float up = smx[d][0];
            float diff = __fsub_rn(up, lo);
            float gdf  = ceilf(fminf(fmaxf(__fdiv_rn(diff, 0.14f), 0.0f), 96.0f));
            float center = __fmul_rn(__fadd_rn(lo, up), 0.5f);
            float half   = __fmul_rn(__fmul_rn(gdf, 0.14f), 0.5f);
            float low2   = __fsub_rn(center, half);
            g_low[b][d]   = low2;
            g_gdimf[b][d] = gdf;
            int gi = (int)gdf;
            gd[d] = gi > 1 ? gi : 1;
        }
        g_stride[b][0] = gd[1] * gd[2];
        g_stride[b][1] = gd[2];
        g_stride[b][2] = 1;
        g_ncell[b]     = gd[0] * gd[1] * gd[2];
    }
}

// ---------------------------------------------------------------------------
// Kernel 2: composite sort keys. key = (cell_id << 12) | particle_index
// ---------------------------------------------------------------------------
__global__ void k_keys(const float* __restrict__ locs) {
    int i = blockIdx.x * blockDim.x + threadIdx.x;
    if (i >= BATCH * NP) return;
    int b = i / NP;
    const float* p = locs + (size_t)i * 3;
    unsigned int id = 0;
    #pragma unroll
    for (int d = 0; d < 3; d++) {
        float c = floorf(__fdiv_rn(__fsub_rn(p[d], g_low[b][d]), 0.14f));
        c = fminf(fmaxf(c, 0.0f), __fsub_rn(g_gdimf[b][d], 1.0f));
        id += (unsigned int)((int)c * g_stride[b][d]);
    }
    g_keys[i] = (id << 12) | (unsigned int)(i - b * NP);
}

// ---------------------------------------------------------------------------
// Kernel 3: rank-by-count sort + fused scatter of all per-particle outputs.
// Also records the sorted cell id per reordered slot (for cell_start build).
// ---------------------------------------------------------------------------
__global__ void k_rank_scatter(const float* __restrict__ locs,
                               const float* __restrict__ data,
                               float* __restrict__ out) {
    const int b = blockIdx.y;
    __shared__ unsigned int sk[NP];
    for (int j = threadIdx.x; j < NP; j += blockDim.x)
        sk[j] = g_keys[b * NP + j];
    __syncthreads();

    const int i = blockIdx.x * blockDim.x + threadIdx.x;   // 0..NP-1
    const unsigned int my = sk[i];
    int r = 0;
    #pragma unroll 16
    for (int j = 0; j < NP; j++)
        r += (sk[j] < my) ? 1 : 0;

    const int src = b * NP + i;
    const int dst = b * NP + r;

    const float* p = locs + (size_t)src * 3;
    float x = p[0], y = p[1], z = p[2];
    float pn = x * x + y * y + z * z;

    out[OFF_LOCS + (size_t)dst * 3 + 0] = x;
    out[OFF_LOCS + (size_t)dst * 3 + 1] = y;
    out[OFF_LOCS + (size_t)dst * 3 + 2] = z;
    g_p4[dst] = make_float4(x, y, z, pn);
    g_scell[dst] = (int)(my >> 12);

    out[OFF_IDXS + dst] = (float)i;

    const float4* d4 = (const float4*)data;      // CC=16 -> 4 float4 per row
    float4* o4 = (float4*)(out + OFF_DATA);
    #pragma unroll
    for (int k = 0; k < 4; k++)
        o4[(size_t)dst * 4 + k] = d4[(size_t)src * 4 + k];
}

// ---------------------------------------------------------------------------
// Kernel 4: cell_start[c] = lower_bound(sorted cell ids, c), c in [0, ncell].
// Grid-stride; actual ncell is ~512 so this is trivial.
// ---------------------------------------------------------------------------
__global__ void k_cellstart() {
    const int b = blockIdx.y;
    const int ncell = g_ncell[b];
    const int* sc = g_scell + b * NP;
    for (int c = blockIdx.x * blockDim.x + threadIdx.x; c <= ncell;
         c += gridDim.x * blockDim.x) {
        int lo = 0, hi = NP;
        while (lo < hi) {
            int mid = (lo + hi) >> 1;
            if (sc[mid] < c) lo = mid + 1; else hi = mid;
        }
        g_cellstart[b][c] = lo;
    }
}

// ---------------------------------------------------------------------------
// Kernel 5: radius search, one WARP per query, cell-range traversal.
// The 27 candidate cells form 9 contiguous, strictly ascending sorted-index
// ranges -> neighbors emitted in ascending reordered order, matching the
// reference. Warp-synchronous ballot/popc compaction, coalesced float4 loads.
// ---------------------------------------------------------------------------
__global__ void k_neighbors(const float* __restrict__ qlocs,
                            float* __restrict__ out) {
    const int b    = blockIdx.y;
    const int lane = threadIdx.x & 31;
    const int m    = blockIdx.x * (blockDim.x >> 5) + (threadIdx.x >> 5);

    const float* q = qlocs + (size_t)(b * MQ + m) * 3;
    const float q0 = q[0], q1 = q[1], q2 = q[2];
    const float qn = q0 * q0 + q1 * q1 + q2 * q2;
    const float R2 = (float)(0.14 * 0.14);

    int cq[3], gd[3];
    #pragma unroll
    for (int d = 0; d < 3; d++) {
        float qd = (d == 0) ? q0 : (d == 1) ? q1 : q2;
        float c = floorf(__fdiv_rn(__fsub_rn(qd, g_low[b][d]), 0.14f));
        int gi = (int)g_gdimf[b][d];
        gd[d] = gi > 1 ? gi : 1;
        int ci = (int)c;
        cq[d] = min(max(ci, 0), gd[d] - 1);
    }
    const int s0 = g_stride[b][0];
    const int s1 = g_stride[b][1];
    const int xlo = max(cq[0] - 1, 0), xhi = min(cq[0] + 1, gd[0] - 1);
    const int ylo = max(cq[1] - 1, 0), yhi = min(cq[1] + 1, gd[1] - 1);
    const int zlo = max(cq[2] - 1, 0), zhi = min(cq[2] + 1, gd[2] - 1);

    const int* cs = g_cellstart[b];
    const float4* P = g_p4 + b * NP;
    float* no = out + OFF_NEI + (size_t)(b * MQ + m) * KMAX;

    int cnt = 0;
    for (int x = xlo; x <= xhi; x++) {
        for (int y = ylo; y <= yhi; y++) {
            const int base = x * s0 + y * s1;
            const int s = __ldg(&cs[base + zlo]);
            const int e = __ldg(&cs[base + zhi + 1]);
            for (int j0 = s; j0 < e; j0 += 32) {
                const int j = j0 + lane;
                bool hit = false;
                if (j < e) {
                    float4 p = __ldg(&P[j]);
                    float cross = q0 * p.x + q1 * p.y + q2 * p.z;
                    float d2 = (qn + p.w) - 2.0f * cross;
                    hit = d2 <= R2;
                }
                unsigned mask = __ballot_sync(0xffffffffu, hit);
                if (hit) {
                    int pos = cnt + __popc(mask & ((1u << lane) - 1));
                    if (pos < KMAX) no[pos] = (float)j;
                }
                cnt += __popc(mask);
                if (cnt >= KMAX) goto fill;
            }
        }
    }
fill:
    for (int k = min(cnt, KMAX) + lane; k < KMAX; k += 32)
        no[k] = -1.0f;
}

// ---------------------------------------------------------------------------
extern "C" void kernel_launch(void* const* d_in, const int* in_sizes, int n_in,
                              void* d_out, int out_size) {
    const float* locs  = (const float*)d_in[0];   // [B,N,3]
    const float* data  = (const float*)d_in[1];   // [B,N,16]
    const float* qlocs = (const float*)d_in[2];   // [B,M,3]
    float* out = (float*)d_out;

    k_bounds<<<BATCH, 256>>>(locs);
    k_keys<<<(BATCH * NP + 255) / 256, 256>>>(locs);

    dim3 g3(NP / 256, BATCH);
    k_rank_scatter<<<g3, 256>>>(locs, data, out);

    dim3 gcs(16, BATCH);
    k_cellstart<<<gcs, 256>>>();

    dim3 g4(MQ / 8, BATCH);     // 8 warps per block, one warp per query
    k_neighbors<<<g4, 256>>>(qlocs, out);
}

// round 3
// speedup vs baseline: 3.1669x; 1.1829x over previous
#include <cuda_runtime.h>

#define BATCH 4
#define NP    4096
#define MQ    4096
#define CC    16
#define KMAX  128

// Output layout (float elements)
#define OFF_LOCS 0
#define OFF_DATA (BATCH*NP*3)                       // 49152
#define OFF_IDXS (OFF_DATA + BATCH*NP*CC)           // 311296
#define OFF_NEI  (OFF_IDXS + BATCH*NP)              // 327680

// ---- device scratch (no allocations allowed) ----
__device__ float        g_low[BATCH][3];
__device__ float        g_gdimf[BATCH][3];
__device__ int          g_stride[BATCH][3];
__device__ __align__(16) unsigned int g_keys[BATCH * NP];
__device__ int          g_scell[BATCH * NP];       // sorted cell id per reordered slot
__device__ float4       g_p4[BATCH * NP];          // reordered particles: x,y,z,|p|^2

// ---------------------------------------------------------------------------
// Kernel 1: per-batch bounds reduction + grid params + sort keys, fused.
// One block (1024 threads) per batch.
// key = (cell_id << 12) | particle_index  (unique -> stable sort == key sort)
// ---------------------------------------------------------------------------
__global__ void k_bounds_keys(const float* __restrict__ locs) {
    const int b = blockIdx.x;
    const int t = threadIdx.x;
    const float* L = locs + (size_t)b * NP * 3;

    float mn[3] = {1e30f, 1e30f, 1e30f};
    float mx[3] = {-1e30f, -1e30f, -1e30f};
    for (int i = t; i < NP; i += 1024) {
        #pragma unroll
        for (int d = 0; d < 3; d++) {
            float v = L[i * 3 + d];
            mn[d] = fminf(mn[d], v);
            mx[d] = fmaxf(mx[d], v);
        }
    }
    #pragma unroll
    for (int o = 16; o > 0; o >>= 1) {
        #pragma unroll
        for (int d = 0; d < 3; d++) {
            mn[d] = fminf(mn[d], __shfl_xor_sync(0xffffffffu, mn[d], o));
            mx[d] = fmaxf(mx[d], __shfl_xor_sync(0xffffffffu, mx[d], o));
        }
    }

    __shared__ float smn[32][3], smx[32][3];
    __shared__ float s_low[3], s_gdimf[3];
    __shared__ int   s_stride[3];
    const int wid = t >> 5, lid = t & 31;
    if (lid == 0) {
        #pragma unroll
        for (int d = 0; d < 3; d++) { smn[wid][d] = mn[d]; smx[wid][d] = mx[d]; }
    }
    __syncthreads();
    if (t < 32) {
        #pragma unroll
        for (int d = 0; d < 3; d++) { mn[d] = smn[t][d]; mx[d] = smx[t][d]; }
        #pragma unroll
        for (int o = 16; o > 0; o >>= 1) {
            #pragma unroll
            for (int d = 0; d < 3; d++) {
                mn[d] = fminf(mn[d], __shfl_xor_sync(0xffffffffu, mn[d], o));
                mx[d] = fmaxf(mx[d], __shfl_xor_sync(0xffffffffu, mx[d], o));
            }
        }
        if (t == 0) {
            int gd[3];
            #pragma unroll
            for (int d = 0; d < 3; d++) {
                float lo = mn[d], up = mx[d];
                float diff = __fsub_rn(up, lo);
                float gdf  = ceilf(fminf(fmaxf(__fdiv_rn(diff, 0.14f), 0.0f), 96.0f));
                float center = __fmul_rn(__fadd_rn(lo, up), 0.5f);
                float half   = __fmul_rn(__fmul_rn(gdf, 0.14f), 0.5f);
                float low2   = __fsub_rn(center, half);
                s_low[d] = low2;  g_low[b][d] = low2;
                s_gdimf[d] = gdf; g_gdimf[b][d] = gdf;
                int gi = (int)gdf;
                gd[d] = gi > 1 ? gi : 1;
            }
            s_stride[0] = gd[1] * gd[2]; s_stride[1] = gd[2]; s_stride[2] = 1;
            g_stride[b][0] = s_stride[0];
            g_stride[b][1] = s_stride[1];
            g_stride[b][2] = 1;
        }
    }
    __syncthreads();

    for (int i = t; i < NP; i += 1024) {
        unsigned int id = 0;
        #pragma unroll
        for (int d = 0; d < 3; d++) {
            float c = floorf(__fdiv_rn(__fsub_rn(L[i * 3 + d], s_low[d]), 0.14f));
            c = fminf(fmaxf(c, 0.0f), __fsub_rn(s_gdimf[d], 1.0f));
            id += (unsigned int)((int)c * s_stride[d]);
        }
        g_keys[b * NP + i] = (id << 12) | (unsigned int)i;
    }
}

// ---------------------------------------------------------------------------
// Kernel 2: rank-by-count sort (uint4 SMEM compares) + fused scatter of all
// per-particle outputs + sorted-cell array. grid = (32, BATCH), 128 threads.
// ---------------------------------------------------------------------------
__global__ void k_rank_scatter(const float* __restrict__ locs,
                               const float* __restrict__ data,
                               float* __restrict__ out) {
    const int b = blockIdx.y;
    __shared__ uint4 sk4[NP / 4];
    const uint4* gk4 = (const uint4*)(g_keys + b * NP);
    for (int j = threadIdx.x; j < NP / 4; j += 128)
        sk4[j] = gk4[j];
    __syncthreads();

    const int i = blockIdx.x * 128 + threadIdx.x;          // 0..NP-1
    const unsigned int my = ((const unsigned int*)sk4)[i];
    int r = 0;
    #pragma unroll 8
    for (int j = 0; j < NP / 4; j++) {
        uint4 v = sk4[j];
        r += (v.x < my) + (v.y < my) + (v.z < my) + (v.w < my);
    }

    const int src = b * NP + i;
    const int dst = b * NP + r;

    const float* p = locs + (size_t)src * 3;
    float x = p[0], y = p[1], z = p[2];
    float pn = x * x + y * y + z * z;

    out[OFF_LOCS + (size_t)dst * 3 + 0] = x;
    out[OFF_LOCS + (size_t)dst * 3 + 1] = y;
    out[OFF_LOCS + (size_t)dst * 3 + 2] = z;
    g_p4[dst] = make_float4(x, y, z, pn);
    g_scell[dst] = (int)(my >> 12);

    out[OFF_IDXS + dst] = (float)i;

    const float4* d4 = (const float4*)data;      // CC=16 -> 4 float4 per row
    float4* o4 = (float4*)(out + OFF_DATA);
    #pragma unroll
    for (int k = 0; k < 4; k++)
        o4[(size_t)dst * 4 + k] = d4[(size_t)src * 4 + k];
}

// ---------------------------------------------------------------------------
// Kernel 3: radius search, one WARP per query. Cell ranges found by
// lane-parallel binary search over the sorted cell-id array (replaces the
// cell_start table + kernel). The <=9 (x,y) row ranges are contiguous and
// strictly ascending in sorted index -> neighbors emitted in ascending
// reordered order, matching the reference exactly.
// ---------------------------------------------------------------------------
__global__ void k_neighbors(const float* __restrict__ qlocs,
                            float* __restrict__ out) {
    const int b    = blockIdx.y;
    const int lane = threadIdx.x & 31;
    const int m    = blockIdx.x * (blockDim.x >> 5) + (threadIdx.x >> 5);

    const float* q = qlocs + (size_t)(b * MQ + m) * 3;
    const float q0 = q[0], q1 = q[1], q2 = q[2];
    const float qn = q0 * q0 + q1 * q1 + q2 * q2;
    const float R2 = (float)(0.14 * 0.14);

    int cq[3], gd[3];
    #pragma unroll
    for (int d = 0; d < 3; d++) {
        float qd = (d == 0) ? q0 : (d == 1) ? q1 : q2;
        float c = floorf(__fdiv_rn(__fsub_rn(qd, g_low[b][d]), 0.14f));
        int gi = (int)g_gdimf[b][d];
        gd[d] = gi > 1 ? gi : 1;
        int ci = (int)c;
        cq[d] = min(max(ci, 0), gd[d] - 1);
    }
    const int s0 = g_stride[b][0];
    const int s1 = g_stride[b][1];
    const int xlo = max(cq[0] - 1, 0), xhi = min(cq[0] + 1, gd[0] - 1);
    const int ylo = max(cq[1] - 1, 0), yhi = min(cq[1] + 1, gd[1] - 1);
    const int zlo = max(cq[2] - 1, 0), zhi = min(cq[2] + 1, gd[2] - 1);

    const int ny = yhi - ylo + 1;
    const int nr = (xhi - xlo + 1) * ny;

    const int* sc = g_scell + b * NP;

    // Lane-parallel lower_bound: lane r < nr finds row-range start,
    // lane r+nr finds row-range end.
    int val = 0;
    if (lane < 2 * nr) {
        int rr = (lane < nr) ? lane : lane - nr;
        int x = xlo + rr / ny;
        int y = ylo + rr % ny;
        int target = x * s0 + y * s1 + ((lane < nr) ? zlo : (zhi + 1));
        int lo = 0, hi = NP;
        while (lo < hi) {
            int mid = (lo + hi) >> 1;
            if (__ldg(&sc[mid]) < target) lo = mid + 1; else hi = mid;
        }
        val = lo;
    }

    const float4* P = g_p4 + b * NP;
    float* no = out + OFF_NEI + (size_t)(b * MQ + m) * KMAX;

    int cnt = 0;
    for (int r = 0; r < nr; r++) {
        const int s = __shfl_sync(0xffffffffu, val, r);
        const int e = __shfl_sync(0xffffffffu, val, r + nr);
        for (int j0 = s; j0 < e; j0 += 32) {
            const int j = j0 + lane;
            bool hit = false;
            if (j < e) {
                float4 p = __ldg(&P[j]);
                float cross = q0 * p.x + q1 * p.y + q2 * p.z;
                float d2 = (qn + p.w) - 2.0f * cross;
                hit = d2 <= R2;
            }
            unsigned mask = __ballot_sync(0xffffffffu, hit);
            if (hit) {
                int pos = cnt + __popc(mask & ((1u << lane) - 1));
                if (pos < KMAX) no[pos] = (float)j;
            }
            cnt += __popc(mask);
            if (cnt >= KMAX) goto fill;
        }
    }
fill:
    for (int k = min(cnt, KMAX) + lane; k < KMAX; k += 32)
        no[k] = -1.0f;
}

// ---------------------------------------------------------------------------
extern "C" void kernel_launch(void* const* d_in, const int* in_sizes, int n_in,
                              void* d_out, int out_size) {
    const float* locs  = (const float*)d_in[0];   // [B,N,3]
    const float* data  = (const float*)d_in[1];   // [B,N,16]
    const float* qlocs = (const float*)d_in[2];   // [B,M,3]
    float* out = (float*)d_out;

    k_bounds_keys<<<BATCH, 1024>>>(locs);

    dim3 g2(NP / 128, BATCH);
    k_rank_scatter<<<g2, 128>>>(locs, data, out);

    dim3 g3(MQ / 8, BATCH);     // 8 warps per block, one warp per query
    k_neighbors<<<g3, 256>>>(qlocs, out);
}

// round 4
// speedup vs baseline: 3.9684x; 1.2531x over previous
#include <cuda_runtime.h>

#define BATCH 4
#define NP    4096
#define MQ    4096
#define CC    16
#define KMAX  128

// Output layout (float elements)
#define OFF_LOCS 0
#define OFF_DATA (BATCH*NP*3)                       // 49152
#define OFF_IDXS (OFF_DATA + BATCH*NP*CC)           // 311296
#define OFF_NEI  (OFF_IDXS + BATCH*NP)              // 327680

// ---- device scratch (no allocations allowed) ----
__device__ float  g_low[BATCH][3];
__device__ float  g_gdimf[BATCH][3];
__device__ int    g_stride[BATCH][3];
__device__ int    g_scell[BATCH * NP];   // sorted cell id per reordered slot
__device__ float4 g_p4[BATCH * NP];      // reordered particles: x,y,z,|p|^2

// Dynamic smem layout for k_prep (per block):
//   float    sl[NP*3]   48 KB   batch locs
//   unsigned sk[NP]     16 KB   sort keys
//   int      sp[256]     1 KB   partial ranks
#define SMEM_PREP ((NP*3)*4 + NP*4 + 256*4)

// ---------------------------------------------------------------------------
// Kernel 1: bounds + grid params + keys + rank-by-count sort + scatter, all
// fused. grid = (NP/128, BATCH), 256 threads. Every block recomputes its
// batch's bounds/keys from a smem copy of locs (min/max are exactly
// order-independent, so all blocks agree bit-for-bit). Thread pairs
// (t, t+128) each scan half the 4096 keys -> 2 warps/SMSP on the rank scan.
// ---------------------------------------------------------------------------
__global__ __launch_bounds__(256) void k_prep(const float* __restrict__ locs,
                                              const float* __restrict__ data,
                                              float* __restrict__ out) {
    extern __shared__ float sdyn[];
    float*        sl = sdyn;                          // [NP*3]
    unsigned int* sk = (unsigned int*)(sdyn + NP*3);  // [NP]
    int*          sp = (int*)(sk + NP);               // [256]

    __shared__ float swmn[8][3], swmx[8][3];
    __shared__ float s_low[3], s_gdimf[3];
    __shared__ int   s_stride[3];

    const int b = blockIdx.y;
    const int t = threadIdx.x;

    // ---- phase 0: stage batch locs into smem (coalesced uint4) ----
    {
        const uint4* src = (const uint4*)(locs + (size_t)b * NP * 3);
        uint4* dstv = (uint4*)sl;
        #pragma unroll
        for (int j = t; j < NP * 3 / 4; j += 256)
            dstv[j] = src[j];
    }
    __syncthreads();

    // ---- phase 1: bounds reduction ----
    float mn[3] = {1e30f, 1e30f, 1e30f};
    float mx[3] = {-1e30f, -1e30f, -1e30f};
    for (int i = t; i < NP; i += 256) {
        #pragma unroll
        for (int d = 0; d < 3; d++) {
            float v = sl[i * 3 + d];
            mn[d] = fminf(mn[d], v);
            mx[d] = fmaxf(mx[d], v);
        }
    }
    #pragma unroll
    for (int o = 16; o > 0; o >>= 1) {
        #pragma unroll
        for (int d = 0; d < 3; d++) {
            mn[d] = fminf(mn[d], __shfl_xor_sync(0xffffffffu, mn[d], o));
            mx[d] = fmaxf(mx[d], __shfl_xor_sync(0xffffffffu, mx[d], o));
        }
    }
    const int wid = t >> 5, lid = t & 31;
    if (lid == 0) {
        #pragma unroll
        for (int d = 0; d < 3; d++) { swmn[wid][d] = mn[d]; swmx[wid][d] = mx[d]; }
    }
    __syncthreads();
    if (t == 0) {
        #pragma unroll
        for (int w = 1; w < 8; w++) {
            #pragma unroll
            for (int d = 0; d < 3; d++) {
                swmn[0][d] = fminf(swmn[0][d], swmn[w][d]);
                swmx[0][d] = fmaxf(swmx[0][d], swmx[w][d]);
            }
        }
        int gd[3];
        #pragma unroll
        for (int d = 0; d < 3; d++) {
            float lo = swmn[0][d], up = swmx[0][d];
            float diff = __fsub_rn(up, lo);
            float gdf  = ceilf(fminf(fmaxf(__fdiv_rn(diff, 0.14f), 0.0f), 96.0f));
            float center = __fmul_rn(__fadd_rn(lo, up), 0.5f);
            float half   = __fmul_rn(__fmul_rn(gdf, 0.14f), 0.5f);
            float low2   = __fsub_rn(center, half);
            s_low[d] = low2;
            s_gdimf[d] = gdf;
            int gi = (int)gdf;
            gd[d] = gi > 1 ? gi : 1;
        }
        s_stride[0] = gd[1] * gd[2]; s_stride[1] = gd[2]; s_stride[2] = 1;
        if (blockIdx.x == 0) {       // publish for k_neighbors
            #pragma unroll
            for (int d = 0; d < 3; d++) {
                g_low[b][d]   = s_low[d];
                g_gdimf[b][d] = s_gdimf[d];
                g_stride[b][d] = s_stride[d];
            }
        }
    }
    __syncthreads();

    // ---- phase 2: keys. key = (cell_id << 12) | particle_index ----
    for (int i = t; i < NP; i += 256) {
        unsigned int id = 0;
        #pragma unroll
        for (int d = 0; d < 3; d++) {
            float c = floorf(__fdiv_rn(__fsub_rn(sl[i * 3 + d], s_low[d]), 0.14f));
            c = fminf(fmaxf(c, 0.0f), __fsub_rn(s_gdimf[d], 1.0f));
            id += (unsigned int)((int)c * s_stride[d]);
        }
        sk[i] = (id << 12) | (unsigned int)i;
    }
    __syncthreads();

    // ---- phase 3: split rank scan (2 threads per particle) ----
    const int il = t & 127;                        // particle slot in block
    const int i  = blockIdx.x * 128 + il;          // particle index in batch
    const unsigned int my = sk[i];
    {
        const uint4* k4 = (const uint4*)sk;
        const int base = (t >> 7) * (NP / 8);      // 0 or 512 uint4s
        int r = 0;
        #pragma unroll 8
        for (int j = 0; j < NP / 8; j++) {
            uint4 v = k4[base + j];
            r += (v.x < my) + (v.y < my) + (v.z < my) + (v.w < my);
        }
        sp[t] = r;
    }
    __syncthreads();

    // ---- phase 4: scatter (first 128 threads) ----
    if (t < 128) {
        const int r   = sp[t] + sp[t + 128];
        const int src = b * NP + i;
        const int dst = b * NP + r;

        float x = sl[i * 3 + 0], y = sl[i * 3 + 1], z = sl[i * 3 + 2];
        float pn = x * x + y * y + z * z;

        out[OFF_LOCS + (size_t)dst * 3 + 0] = x;
        out[OFF_LOCS + (size_t)dst * 3 + 1] = y;
        out[OFF_LOCS + (size_t)dst * 3 + 2] = z;
        g_p4[dst] = make_float4(x, y, z, pn);
        g_scell[dst] = (int)(my >> 12);
        out[OFF_IDXS + dst] = (float)i;

        const float4* d4 = (const float4*)data;   // CC=16 -> 4 float4 per row
        float4* o4 = (float4*)(out + OFF_DATA);
        #pragma unroll
        for (int k = 0; k < 4; k++)
            o4[(size_t)dst * 4 + k] = d4[(size_t)src * 4 + k];
    }
}

// ---------------------------------------------------------------------------
// Kernel 2: radius search, one WARP per query. Cell ranges via lane-parallel
// binary search over the sorted cell-id array. The <=9 (x,y) row ranges are
// contiguous and strictly ascending in sorted index -> neighbors emitted in
// ascending reordered order, matching the reference exactly.
// ---------------------------------------------------------------------------
__global__ void k_neighbors(const float* __restrict__ qlocs,
                            float* __restrict__ out) {
    const int b    = blockIdx.y;
    const int lane = threadIdx.x & 31;
    const int m    = blockIdx.x * (blockDim.x >> 5) + (threadIdx.x >> 5);

    const float* q = qlocs + (size_t)(b * MQ + m) * 3;
    const float q0 = q[0], q1 = q[1], q2 = q[2];
    const float qn = q0 * q0 + q1 * q1 + q2 * q2;
    const float R2 = (float)(0.14 * 0.14);

    int cq[3], gd[3];
    #pragma unroll
    for (int d = 0; d < 3; d++) {
        float qd = (d == 0) ? q0 : (d == 1) ? q1 : q2;
        float c = floorf(__fdiv_rn(__fsub_rn(qd, g_low[b][d]), 0.14f));
        int gi = (int)g_gdimf[b][d];
        gd[d] = gi > 1 ? gi : 1;
        int ci = (int)c;
        cq[d] = min(max(ci, 0), gd[d] - 1);
    }
    const int s0 = g_stride[b][0];
    const int s1 = g_stride[b][1];
    const int xlo = max(cq[0] - 1, 0), xhi = min(cq[0] + 1, gd[0] - 1);
    const int ylo = max(cq[1] - 1, 0), yhi = min(cq[1] + 1, gd[1] - 1);
    const int zlo = max(cq[2] - 1, 0), zhi = min(cq[2] + 1, gd[2] - 1);

    const int ny = yhi - ylo + 1;
    const int nr = (xhi - xlo + 1) * ny;

    const int* sc = g_scell + b * NP;

    // Lane-parallel lower_bound: lane r < nr finds row-range start,
    // lane r+nr finds row-range end.
    int val = 0;
    if (lane < 2 * nr) {
        int rr = (lane < nr) ? lane : lane - nr;
        int x = xlo + rr / ny;
        int y = ylo + rr % ny;
        int target = x * s0 + y * s1 + ((lane < nr) ? zlo : (zhi + 1));
        int lo = 0, hi = NP;
        while (lo < hi) {
            int mid = (lo + hi) >> 1;
            if (__ldg(&sc[mid]) < target) lo = mid + 1; else hi = mid;
        }
        val = lo;
    }

    const float4* P = g_p4 + b * NP;
    float* no = out + OFF_NEI + (size_t)(b * MQ + m) * KMAX;

    int cnt = 0;
    for (int r = 0; r < nr; r++) {
        const int s = __shfl_sync(0xffffffffu, val, r);
        const int e = __shfl_sync(0xffffffffu, val, r + nr);
        for (int j0 = s; j0 < e; j0 += 32) {
            const int j = j0 + lane;
            bool hit = false;
            if (j < e) {
                float4 p = __ldg(&P[j]);
                float cross = q0 * p.x + q1 * p.y + q2 * p.z;
                float d2 = (qn + p.w) - 2.0f * cross;
                hit = d2 <= R2;
            }
            unsigned mask = __ballot_sync(0xffffffffu, hit);
            if (hit) {
                int pos = cnt + __popc(mask & ((1u << lane) - 1));
                if (pos < KMAX) no[pos] = (float)j;
            }
            cnt += __popc(mask);
            if (cnt >= KMAX) goto fill;
        }
    }
fill:
    for (int k = min(cnt, KMAX) + lane; k < KMAX; k += 32)
        no[k] = -1.0f;
}

// ---------------------------------------------------------------------------
extern "C" void kernel_launch(void* const* d_in, const int* in_sizes, int n_in,
                              void* d_out, int out_size) {
    const float* locs  = (const float*)d_in[0];   // [B,N,3]
    const float* data  = (const float*)d_in[1];   // [B,N,16]
    const float* qlocs = (const float*)d_in[2];   // [B,M,3]
    float* out = (float*)d_out;

    cudaFuncSetAttribute(k_prep,
                         cudaFuncAttributeMaxDynamicSharedMemorySize,
                         SMEM_PREP);
    dim3 g1(NP / 128, BATCH);
    k_prep<<<g1, 256, SMEM_PREP>>>(locs, data, out);

    dim3 g2(MQ / 8, BATCH);     // 8 warps per block, one warp per query
    k_neighbors<<<g2, 256>>>(qlocs, out);
}